// round 16
// baseline (speedup 1.0000x reference)
#include <cuda_runtime.h>
#include <cuda_fp16.h>
#include <cstdint>

#define MM 4096
#define NN 4096
#define PLANE (MM * NN)
#define MAX_IT 20
#define F_SIGMA 14.285714285714285f   // 1/(7*0.01)
#define F_TAU 0.01f
#define F_LT 0.07f                    // LAMBDA_ROF * TAU
#define F_THETA 0.5f
#define F_INV_DENOM (1.0f / 1.07f)

#define NT 288          // 9 warps; 260 active threads x 2 cols = 520 cols
#define NACT 260
#define SW 524          // smem width: 1 pad + 520 + 3 pad

// Scratch (__device__ globals; allocation-free rule)
__device__ float   g_x[2][2][PLANE];   // [pair][0]=x_odd-iter, [pair][1]=x_even-iter
__device__ __half2 g_y[2][PLANE];      // ping-pong dual, (y0,y1) packed
__device__ __half2 g_w[PLANE];         // (w0,w1) packed fp16

__device__ __forceinline__ float clip1(float v) {
    return fminf(fmaxf(v, -1.0f), 1.0f);
}
__device__ __forceinline__ float XT(float a, float b) {
    return a + F_THETA * (a - b);
}

// One-time conversion of w to packed fp16, 4 pixels/thread.
__global__ __launch_bounds__(256) void w_convert(const float* __restrict__ w) {
    const int idx = (blockIdx.x * blockDim.x + threadIdx.x) * 4;
    const float4 a = *reinterpret_cast<const float4*>(w + idx);
    const float4 b = *reinterpret_cast<const float4*>(w + PLANE + idx);
    __half2 pk[4];
    pk[0] = __floats2half2_rn(a.x, b.x);
    pk[1] = __floats2half2_rn(a.y, b.y);
    pk[2] = __floats2half2_rn(a.z, b.z);
    pk[3] = __floats2half2_rn(a.w, b.w);
    *reinterpret_cast<uint4*>(g_w + idx) = *reinterpret_cast<uint4*>(pk);
}

// TWO fused primal-dual iterations per kernel, row-streaming skewed pipeline,
// 2 adjacent pixels per thread. Per step s (3 barriers):
//   A: xt row s -> smem ring + regs     [bar]
//   B: y1 row s-1 (h1 odd col -> smem)  [bar]
//   C: x1/xt1 row s-1 (xt1 ring smem+regs)
//   D: y2 row s-2 (h2 odd col -> smem)  [bar]
//   E: x2 row s-2 -> gmem
// Vertical carries in registers; horizontal comm register-local within the
// pair, smem only across threads. Numerics identical to R12 (rel_err 3.24e-5).
template<bool FIRST, bool LAST>
__global__ __launch_bounds__(NT, 4) void pd_fused2(
    int pair, int yin_b, int yout_b,
    const float* __restrict__ img,
    const float* __restrict__ y0f,
    float* __restrict__ dout)
{
    __shared__ float s_xt [2][SW];
    __shared__ float s_xt1[2][SW];
    __shared__ float s_h1[SW];
    __shared__ float s_h2[SW];

    const int lc = threadIdx.x;
    const int J0 = blockIdx.x * 512;
    const int b  = blockIdx.y;                  // 0..73
    const int R0 = b * 55 + min(b, 26);
    const int RS = 55 + (b < 26 ? 1 : 0);
    const int R1 = R0 + RS;

    const bool act = (lc < NACT);
    const int c0 = 2 * lc;                      // logical col offset in strip
    const int j0 = J0 - 4 + c0;                 // global col of even pixel
    const bool jok = act && (j0 >= 0) && (j0 < NN);  // pair fully in/out
    const bool core = jok && (j0 >= J0) && (j0 < J0 + 512);

    // zero the padding cells once (read-only thereafter)
    if (lc == 0) {
        #pragma unroll
        for (int r = 0; r < 2; ++r) {
            s_xt[r][0] = 0.f; s_xt1[r][0] = 0.f;
            for (int q = SW - 3; q < SW; ++q) { s_xt[r][q] = 0.f; s_xt1[r][q] = 0.f; }
        }
        s_h1[0] = 0.f; s_h2[0] = 0.f;
        for (int q = SW - 3; q < SW; ++q) { s_h1[q] = 0.f; s_h2[q] = 0.f; }
    }

    const float* __restrict__ xA = FIRST ? img : g_x[pair ^ 1][1];
    const float* __restrict__ xB = FIRST ? img : g_x[pair ^ 1][0];
    const __half2* __restrict__ yin = g_y[yin_b];
    float*   __restrict__ x1out = g_x[pair][0];
    float*   __restrict__ x2out = g_x[pair][1];
    __half2* __restrict__ yout  = g_y[yout_b];

    const int y1_lo = max(R0 - 2, 0), y1_hi = min(R1, MM - 1);
    const int x1_lo = max(R0 - 1, 0), x1_hi = min(R1, MM - 1);
    const int y2_lo = x1_lo,          y2_hi = min(R1 - 1, MM - 1);
    const int s0 = max(R0 - 2, 0), s_end = R1 + 1;

    // per-column register state (vertical carries), [0]=even col, [1]=odd col
    float xAp[2] = {0,0}, imp[2] = {0,0}, x1p[2] = {0,0};
    float v1p[2] = {0,0}, v2p[2] = {0,0};
    float y1p0[2] = {0,0}, y1p1[2] = {0,0};
    float w0p[2] = {0,0}, w1p[2] = {0,0};
    float xt_prev[2] = {0,0};     // xt row s-1 (own cols)
    float xt1_m1[2] = {0,0};      // xt1 row s-2 (own cols)

    // inputs for the current step (xt-inputs row s; w/y/img row s-1)
    float nxA[2] = {0,0}, nxB[2] = {0,0}, nim[2] = {0,0};
    float ny0[2] = {0,0}, ny1[2] = {0,0}, nw0[2] = {0,0}, nw1[2] = {0,0};

    // initial prefetch for step s0
    if (jok) {
        if (s0 <= MM - 1) {
            const float2 a = *reinterpret_cast<const float2*>(xA + s0 * NN + j0);
            nxA[0] = a.x; nxA[1] = a.y;
            if (!FIRST) {
                const float2 bb = *reinterpret_cast<const float2*>(xB + s0 * NN + j0);
                nxB[0] = bb.x; nxB[1] = bb.y;
            }
        }
        const int rp = s0 - 1;
        if (rp >= 0) {
            uint2 wu = *reinterpret_cast<const uint2*>(g_w + rp * NN + j0);
            const __half2 w0h = *reinterpret_cast<__half2*>(&wu.x);
            const __half2 w1h = *reinterpret_cast<__half2*>(&wu.y);
            nw0[0] = __low2float(w0h); nw1[0] = __high2float(w0h);
            nw0[1] = __low2float(w1h); nw1[1] = __high2float(w1h);
            if (FIRST) {
                const float2 a = *reinterpret_cast<const float2*>(y0f + rp * NN + j0);
                const float2 bb = *reinterpret_cast<const float2*>(y0f + PLANE + rp * NN + j0);
                ny0[0] = a.x; ny0[1] = a.y; ny1[0] = bb.x; ny1[1] = bb.y;
            } else {
                uint2 yu = *reinterpret_cast<const uint2*>(yin + rp * NN + j0);
                const __half2 ya = *reinterpret_cast<__half2*>(&yu.x);
                const __half2 yb = *reinterpret_cast<__half2*>(&yu.y);
                ny0[0] = __low2float(ya); ny1[0] = __high2float(ya);
                ny0[1] = __low2float(yb); ny1[1] = __high2float(yb);
                const float2 c = *reinterpret_cast<const float2*>(img + rp * NN + j0);
                nim[0] = c.x; nim[1] = c.y;
            }
        }
    }

    for (int s = s0; s <= s_end; ++s) {
        const int r1 = s - 1;
        const int r2 = s - 2;

        // ---- phase A: xt row s -> smem ring + regs
        float xt_cur[2] = {0.f, 0.f};
        if (act) {
            const bool ok = jok && (s <= MM - 1);
            #pragma unroll
            for (int q = 0; q < 2; ++q) {
                const float xts = FIRST ? nxA[q] : XT(nxA[q], nxB[q]);
                xt_cur[q] = ok ? xts : 0.f;
                s_xt[s & 1][c0 + 1 + q] = xt_cur[q];
            }
        }

        // ---- prefetch step s+1 (in flight across this step's barriers)
        float pxA[2] = {0,0}, pxB[2] = {0,0}, pim[2] = {0,0};
        float py0[2] = {0,0}, py1[2] = {0,0}, pw0[2] = {0,0}, pw1[2] = {0,0};
        if (jok) {
            const int sn = s + 1;
            if (sn <= s_end && sn <= MM - 1) {
                const float2 a = *reinterpret_cast<const float2*>(xA + sn * NN + j0);
                pxA[0] = a.x; pxA[1] = a.y;
                if (!FIRST) {
                    const float2 bb = *reinterpret_cast<const float2*>(xB + sn * NN + j0);
                    pxB[0] = bb.x; pxB[1] = bb.y;
                }
            }
            if (s >= 0 && s <= y1_hi) {
                uint2 wu = *reinterpret_cast<const uint2*>(g_w + s * NN + j0);
                const __half2 w0h = *reinterpret_cast<__half2*>(&wu.x);
                const __half2 w1h = *reinterpret_cast<__half2*>(&wu.y);
                pw0[0] = __low2float(w0h); pw1[0] = __high2float(w0h);
                pw0[1] = __low2float(w1h); pw1[1] = __high2float(w1h);
                if (FIRST) {
                    const float2 a = *reinterpret_cast<const float2*>(y0f + s * NN + j0);
                    const float2 bb = *reinterpret_cast<const float2*>(y0f + PLANE + s * NN + j0);
                    py0[0] = a.x; py0[1] = a.y; py1[0] = bb.x; py1[1] = bb.y;
                } else {
                    uint2 yu = *reinterpret_cast<const uint2*>(yin + s * NN + j0);
                    const __half2 ya = *reinterpret_cast<__half2*>(&yu.x);
                    const __half2 yb = *reinterpret_cast<__half2*>(&yu.y);
                    py0[0] = __low2float(ya); py1[0] = __high2float(ya);
                    py0[1] = __low2float(yb); py1[1] = __high2float(yb);
                    const float2 c = *reinterpret_cast<const float2*>(img + s * NN + j0);
                    pim[0] = c.x; pim[1] = c.y;
                }
            }
        }
        __syncthreads();

        // ---- phase B: dual iter-1, row r1
        float v1c[2] = {0,0}, y1c0[2] = {0,0}, y1c1[2] = {0,0}, h1c[2] = {0,0};
        const bool doB = jok && (r1 >= y1_lo) && (r1 <= y1_hi);
        if (doB) {
            const float xt_r = s_xt[(s - 1) & 1][c0 + 3];   // right of odd col
            #pragma unroll
            for (int q = 0; q < 2; ++q) {
                const int j = j0 + q;
                const float xtc = xt_prev[q];
                const float rgt = q ? xt_r : xt_prev[1];
                const float gx = (j < NN - 1) ? (rgt - xtc) : 0.f;
                const float gy = (r1 < MM - 1) ? (xt_cur[q] - xtc) : 0.f;
                y1c0[q] = clip1(ny0[q] + F_SIGMA * nw0[q] * gx);
                y1c1[q] = clip1(ny1[q] + F_SIGMA * nw1[q] * gy);
                h1c[q] = nw0[q] * y1c0[q];
                v1c[q] = nw1[q] * y1c1[q];
            }
            s_h1[c0 + 2] = h1c[1];      // only odd col crosses threads
        }
        __syncthreads();

        // ---- phase C: primal + relax iter-1, row r1
        float x1c[2] = {0,0}, xt1_0[2] = {0,0};
        const bool doC = jok && (r1 >= x1_lo) && (r1 <= x1_hi);
        if (doC) {
            const float h_lft = s_h1[c0];                   // left of even col
            #pragma unroll
            for (int q = 0; q < 2; ++q) {
                const int j = j0 + q;
                const float h_c = h1c[q];
                const float h_l = q ? h1c[0] : h_lft;
                float dh;
                if (j == 0)            dh = h_c;
                else if (j == NN - 1)  dh = -h_l;
                else                   dh = h_c - h_l;
                float dv;
                if (r1 == 0)           dv = v1c[q];
                else if (r1 == MM - 1) dv = -v1p[q];
                else                   dv = v1c[q] - v1p[q];
                const float imv = FIRST ? xAp[q] : nim[q];  // img row r1
                x1c[q] = (xAp[q] + F_TAU * (dh + dv) + F_LT * imv) * F_INV_DENOM;
                xt1_0[q] = x1c[q] + F_THETA * (x1c[q] - xAp[q]);
                s_xt1[r1 & 1][c0 + 1 + q] = xt1_0[q];
            }
            if (!LAST && core && r1 >= R0 && r1 < R1) {
                float2 st; st.x = x1c[0]; st.y = x1c[1];
                *reinterpret_cast<float2*>(x1out + r1 * NN + j0) = st;
            }
        }
        // (no barrier needed: phase D reads the xt1 ring slot written last step)

        // ---- phase D: dual iter-2, row r2
        float v2c[2] = {0,0}, h2c[2] = {0,0};
        const bool doD = jok && (r2 >= y2_lo) && (r2 <= y2_hi);
        if (doD) {
            const float xt1_r = s_xt1[(s - 2) & 1][c0 + 3];
            float y20[2], y21[2];
            #pragma unroll
            for (int q = 0; q < 2; ++q) {
                const int j = j0 + q;
                const float xtc = xt1_m1[q];
                const float rgt = q ? xt1_r : xt1_m1[1];
                const float gx = (j < NN - 1) ? (rgt - xtc) : 0.f;
                const float gy = (r2 < MM - 1) ? (xt1_0[q] - xtc) : 0.f;
                y20[q] = clip1(y1p0[q] + F_SIGMA * w0p[q] * gx);
                y21[q] = clip1(y1p1[q] + F_SIGMA * w1p[q] * gy);
                h2c[q] = w0p[q] * y20[q];
                v2c[q] = w1p[q] * y21[q];
            }
            s_h2[c0 + 2] = h2c[1];
            if (!LAST && core && r2 >= R0 && r2 < R1) {
                uint2 st;
                __half2 a = __floats2half2_rn(y20[0], y21[0]);
                __half2 bb = __floats2half2_rn(y20[1], y21[1]);
                st.x = *reinterpret_cast<unsigned int*>(&a);
                st.y = *reinterpret_cast<unsigned int*>(&bb);
                *reinterpret_cast<uint2*>(yout + r2 * NN + j0) = st;
            }
        }
        __syncthreads();

        // ---- phase E: primal iter-2, row r2 (core only) -> gmem
        if (core && r2 >= R0 && r2 < R1) {
            const float h_lft = s_h2[c0];
            float x2v[2];
            #pragma unroll
            for (int q = 0; q < 2; ++q) {
                const int j = j0 + q;
                const float h_c = h2c[q];
                const float h_l = q ? h2c[0] : h_lft;
                float dh;
                if (j == 0)            dh = h_c;
                else if (j == NN - 1)  dh = -h_l;
                else                   dh = h_c - h_l;
                float dv;
                if (r2 == 0)           dv = v2c[q];
                else if (r2 == MM - 1) dv = -v2p[q];
                else                   dv = v2c[q] - v2p[q];
                const float x2 = (x1p[q] + F_TAU * (dh + dv) + F_LT * imp[q]) * F_INV_DENOM;
                x2v[q] = LAST ? (x2 + F_THETA * (x2 - x1p[q])) : x2;
            }
            float2 st; st.x = x2v[0]; st.y = x2v[1];
            float* outp = LAST ? dout : x2out;
            *reinterpret_cast<float2*>(outp + r2 * NN + j0) = st;
        }

        // ---- shift per-column state
        #pragma unroll
        for (int q = 0; q < 2; ++q) {
            v1p[q] = v1c[q]; v2p[q] = v2c[q]; x1p[q] = x1c[q];
            y1p0[q] = y1c0[q]; y1p1[q] = y1c1[q];
            w0p[q] = nw0[q]; w1p[q] = nw1[q];
            imp[q] = FIRST ? xAp[q] : nim[q];
            xAp[q] = nxA[q];
            xt_prev[q] = xt_cur[q]; xt1_m1[q] = xt1_0[q];
            nxA[q] = pxA[q]; nxB[q] = pxB[q]; nim[q] = pim[q];
            nw0[q] = pw0[q]; nw1[q] = pw1[q]; ny0[q] = py0[q]; ny1[q] = py1[q];
        }
    }
}

extern "C" void kernel_launch(void* const* d_in, const int* in_sizes, int n_in,
                              void* d_out, int out_size) {
    const float* img = (const float*)d_in[0];   // [1, 4096, 4096]
    const float* w   = (const float*)d_in[1];   // [2, 4096, 4096]
    const float* y0  = (const float*)d_in[2];   // [2, 4096, 4096]
    float* out = (float*)d_out;

    w_convert<<<PLANE / (4 * 256), 256>>>(w);

    dim3 grid(8, 74);   // 592 blocks = 148 SMs x 4 CTAs -> single wave

    // Fused kernel t does iterations 2t+1, 2t+2 (t = 0..9).
    for (int t = 0; t < MAX_IT / 2; ++t) {
        const int pair   = t & 1;
        const int yout_b = t & 1;
        const int yin_b  = (t + 1) & 1;
        if (t == 0)
            pd_fused2<true,  false><<<grid, NT>>>(pair, yin_b, yout_b, img, y0, out);
        else if (t == MAX_IT / 2 - 1)
            pd_fused2<false, true ><<<grid, NT>>>(pair, yin_b, yout_b, img, y0, out);
        else
            pd_fused2<false, false><<<grid, NT>>>(pair, yin_b, yout_b, img, y0, out);
    }
}

// round 17
// speedup vs baseline: 1.1374x; 1.1374x over previous
#include <cuda_runtime.h>
#include <cuda_fp16.h>
#include <cstdint>

#define MM 4096
#define NN 4096
#define PLANE (MM * NN)
#define MAX_IT 20
#define F_SIGMA 14.285714285714285f   // 1/(7*0.01)
#define F_TAU 0.01f
#define F_LT 0.07f                    // LAMBDA_ROF * TAU
#define F_THETA 0.5f
#define F_INV_DENOM (1.0f / 1.07f)

#define NT 288          // 9 warps; 260 active threads (256 core + 4 halo cols)
#define WID 260         // strip width incl. 2+2 halo cols (core 256)

// Scratch (__device__ globals; allocation-free rule)
__device__ float   g_x[2][2][PLANE];   // [pair][0]=x_odd-iter, [pair][1]=x_even-iter
__device__ __half2 g_y[2][PLANE];      // ping-pong dual, (y0,y1) packed
__device__ __half2 g_w[PLANE];         // (w0,w1) packed fp16

__device__ __forceinline__ float clip1(float v) {
    return fminf(fmaxf(v, -1.0f), 1.0f);
}
__device__ __forceinline__ float XT(float a, float b) {
    return a + F_THETA * (a - b);
}

// One-time conversion of w to packed fp16, 4 pixels/thread.
__global__ __launch_bounds__(256) void w_convert(const float* __restrict__ w) {
    const int idx = (blockIdx.x * blockDim.x + threadIdx.x) * 4;
    const float4 a = *reinterpret_cast<const float4*>(w + idx);
    const float4 b = *reinterpret_cast<const float4*>(w + PLANE + idx);
    __half2 pk[4];
    pk[0] = __floats2half2_rn(a.x, b.x);
    pk[1] = __floats2half2_rn(a.y, b.y);
    pk[2] = __floats2half2_rn(a.z, b.z);
    pk[3] = __floats2half2_rn(a.w, b.w);
    *reinterpret_cast<uint4*>(g_w + idx) = *reinterpret_cast<uint4*>(pk);
}

// TWO fused primal-dual iterations per kernel, row-streaming skewed pipeline,
// 1 pixel/thread (R12 structure), 256-col strips, 4 CTAs/SM, 3 barriers/row:
//   A: xt row s -> smem ring            [bar]
//   B: y1 row s-1 (h1 -> smem)          [bar]
//   C: x1/xt1 row s-1 (xt1 ring -> smem)
//   D: y2 row s-2 (h2 -> smem)          [bar]
//   E: x2 row s-2 -> gmem
// (No C->D barrier: phase D reads the xt1 ring slot written one full step
//  earlier; the post-D / post-A / post-B barriers order it. Validated in R15 —
//  identical rel_err.)
template<bool FIRST, bool LAST>
__global__ __launch_bounds__(NT, 4) void pd_fused2(
    int pair, int yin_b, int yout_b,
    const float* __restrict__ img,
    const float* __restrict__ y0f,
    float* __restrict__ dout)
{
    __shared__ float s_xt [2][WID + 4];
    __shared__ float s_xt1[2][WID + 4];
    __shared__ float s_h1[WID + 4];
    __shared__ float s_h2[WID + 4];

    const int lc = threadIdx.x;
    const int J0 = blockIdx.x * 256;
    const int b  = blockIdx.y;                  // 0..36
    const int R0 = b * 110 + min(b, 26);
    const int RS = 110 + (b < 26 ? 1 : 0);
    const int R1 = R0 + RS;

    const int j = J0 - 2 + lc;
    const bool act = (lc < WID);
    const bool jok = act && (j >= 0) && (j < NN);

    const float* __restrict__ xA = FIRST ? img : g_x[pair ^ 1][1];
    const float* __restrict__ xB = FIRST ? img : g_x[pair ^ 1][0];
    const __half2* __restrict__ yin = g_y[yin_b];
    float*   __restrict__ x1out = g_x[pair][0];
    float*   __restrict__ x2out = g_x[pair][1];
    __half2* __restrict__ yout  = g_y[yout_b];

    const int y1_lo = max(R0 - 2, 0), y1_hi = min(R1, MM - 1);
    const int x1_lo = max(R0 - 1, 0), x1_hi = min(R1, MM - 1);
    const int y2_lo = x1_lo,          y2_hi = min(R1 - 1, MM - 1);
    const int s0 = max(R0 - 2, 0), s_end = R1 + 1;

    // per-column register state (vertical carries)
    float xAp = 0.f, imp = 0.f, x1p = 0.f, v1p = 0.f, v2p = 0.f;
    float y1p0 = 0.f, y1p1 = 0.f;
    float xt1_m1 = 0.f;                 // xt1 row s-2 (own col)
    __half2 wp = __floats2half2_rn(0.f, 0.f);

    // prefetched inputs for the current step
    float nxA = 0.f, nxB = 0.f, nim = 0.f, ny0 = 0.f, ny1 = 0.f;
    __half2 nyh = wp, nw = wp;
    {
        if (jok && s0 <= MM - 1) {
            nxA = xA[s0 * NN + j];
            if (!FIRST) nxB = xB[s0 * NN + j];
        }
        const int rp = s0 - 1;
        if (jok && rp >= 0) {
            nw = g_w[rp * NN + j];
            if (FIRST) { ny0 = y0f[rp * NN + j]; ny1 = y0f[PLANE + rp * NN + j]; }
            else {
                nyh = yin[rp * NN + j];
                nim = img[rp * NN + j];
            }
        }
    }

    for (int s = s0; s <= s_end; ++s) {
        // ---- phase A: xt row s into smem ring
        if (act) {
            const float xts = FIRST ? nxA : XT(nxA, nxB);
            s_xt[s & 1][lc] = (jok && s <= MM - 1) ? xts : 0.f;
        }
        // issue prefetch for step s+1 (in flight across this step's barriers)
        float pxA = 0.f, pxB = 0.f, pim = 0.f, py0 = 0.f, py1 = 0.f;
        __half2 pyh = __floats2half2_rn(0.f, 0.f), pw = pyh;
        {
            const int sn = s + 1;
            if (jok && sn <= s_end && sn <= MM - 1) {
                pxA = xA[sn * NN + j];
                if (!FIRST) pxB = xB[sn * NN + j];
            }
            if (jok && s >= 0 && s <= y1_hi) {
                pw = g_w[s * NN + j];
                if (FIRST) { py0 = y0f[s * NN + j]; py1 = y0f[PLANE + s * NN + j]; }
                else {
                    pyh = yin[s * NN + j];
                    pim = img[s * NN + j];
                }
            }
        }
        __syncthreads();

        // ---- phase B: dual iter-1, row s-1
        const int r1 = s - 1;
        float v1c = 0.f, y1c0 = 0.f, y1c1 = 0.f;
        if (jok && lc < WID - 1 && r1 >= y1_lo && r1 <= y1_hi) {
            const float xtc = s_xt[(s - 1) & 1][lc];
            const float gx = (j < NN - 1) ? s_xt[(s - 1) & 1][lc + 1] - xtc : 0.f;
            const float gy = (r1 < MM - 1) ? s_xt[s & 1][lc] - xtc : 0.f;
            const float w0 = __low2float(nw), w1 = __high2float(nw);
            float yo0, yo1;
            if (FIRST) { yo0 = ny0; yo1 = ny1; }
            else { yo0 = __low2float(nyh); yo1 = __high2float(nyh); }
            y1c0 = clip1(yo0 + F_SIGMA * w0 * gx);
            y1c1 = clip1(yo1 + F_SIGMA * w1 * gy);
            s_h1[lc] = w0 * y1c0;
            v1c = w1 * y1c1;
        }
        __syncthreads();

        // ---- phase C: primal + relax iter-1, row s-1
        float x1c = 0.f, xt1_0 = 0.f;
        if (jok && lc >= 1 && lc < WID - 1 && r1 >= x1_lo && r1 <= x1_hi) {
            const float h_c = s_h1[lc];
            float dh;
            if (j == 0) dh = h_c;
            else { const float h_l = s_h1[lc - 1]; dh = (j == NN - 1) ? -h_l : h_c - h_l; }
            float dv;
            if (r1 == 0) dv = v1c;
            else dv = (r1 == MM - 1) ? -v1p : v1c - v1p;
            const float imv = FIRST ? xAp : nim;        // img[s-1]
            x1c = (xAp + F_TAU * (dh + dv) + F_LT * imv) * F_INV_DENOM;
            xt1_0 = x1c + F_THETA * (x1c - xAp);
            s_xt1[r1 & 1][lc] = xt1_0;
            if (!LAST && lc >= 2 && lc < WID - 2 && r1 >= R0 && r1 < R1)
                x1out[r1 * NN + j] = x1c;
        }
        // (no barrier: phase D reads the xt1 ring slot written one step earlier)

        // ---- phase D: dual iter-2, row s-2
        const int r2 = s - 2;
        float v2c = 0.f;
        if (jok && lc >= 1 && lc < WID - 2 && r2 >= y2_lo && r2 <= y2_hi) {
            const float xt1c = xt1_m1;
            const float gx = (j < NN - 1) ? s_xt1[r2 & 1][lc + 1] - xt1c : 0.f;
            const float gy = (r2 < MM - 1) ? xt1_0 - xt1c : 0.f;
            const float w0 = __low2float(wp), w1 = __high2float(wp);
            const float y20 = clip1(y1p0 + F_SIGMA * w0 * gx);
            const float y21 = clip1(y1p1 + F_SIGMA * w1 * gy);
            s_h2[lc] = w0 * y20;
            v2c = w1 * y21;
            if (!LAST && lc >= 2 && r2 >= R0 && r2 < R1)
                yout[r2 * NN + j] = __floats2half2_rn(y20, y21);
        }
        __syncthreads();

        // ---- phase E: primal iter-2, row s-2 (core only) -> gmem
        if (lc >= 2 && lc < WID - 2 && r2 >= R0 && r2 < R1) {
            const float h_c = s_h2[lc];
            float dh;
            if (j == 0) dh = h_c;
            else { const float h_l = s_h2[lc - 1]; dh = (j == NN - 1) ? -h_l : h_c - h_l; }
            float dv;
            if (r2 == 0) dv = v2c;
            else dv = (r2 == MM - 1) ? -v2p : v2c - v2p;
            const float x2 = (x1p + F_TAU * (dh + dv) + F_LT * imp) * F_INV_DENOM;
            if (LAST) dout[r2 * NN + j] = x2 + F_THETA * (x2 - x1p);
            else      x2out[r2 * NN + j] = x2;
        }

        // ---- shift per-column state (order matters: imp before xAp)
        v1p = v1c; v2p = v2c; x1p = x1c;
        y1p0 = y1c0; y1p1 = y1c1;
        xt1_m1 = xt1_0;
        wp = nw;
        imp = FIRST ? xAp : nim;
        xAp = nxA;
        nxA = pxA; nxB = pxB; nim = pim; nw = pw; nyh = pyh; ny0 = py0; ny1 = py1;
    }
}

extern "C" void kernel_launch(void* const* d_in, const int* in_sizes, int n_in,
                              void* d_out, int out_size) {
    const float* img = (const float*)d_in[0];   // [1, 4096, 4096]
    const float* w   = (const float*)d_in[1];   // [2, 4096, 4096]
    const float* y0  = (const float*)d_in[2];   // [2, 4096, 4096]
    float* out = (float*)d_out;

    w_convert<<<PLANE / (4 * 256), 256>>>(w);

    dim3 grid(16, 37);   // 592 blocks = 148 SMs x 4 CTAs -> single wave

    // Fused kernel t does iterations 2t+1, 2t+2 (t = 0..9).
    for (int t = 0; t < MAX_IT / 2; ++t) {
        const int pair   = t & 1;
        const int yout_b = t & 1;
        const int yin_b  = (t + 1) & 1;
        if (t == 0)
            pd_fused2<true,  false><<<grid, NT>>>(pair, yin_b, yout_b, img, y0, out);
        else if (t == MAX_IT / 2 - 1)
            pd_fused2<false, true ><<<grid, NT>>>(pair, yin_b, yout_b, img, y0, out);
        else
            pd_fused2<false, false><<<grid, NT>>>(pair, yin_b, yout_b, img, y0, out);
    }
}